// round 1
// baseline (speedup 1.0000x reference)
#include <cuda_runtime.h>
#include <cstdint>

// Fused: out = (x + residual^T); h = LN(out)*g+b; hd = relu(h@Wd^T + bd);
//        out += hd@Wu^T + bu
// S=4096, B=8, D=1024, BN=128 -> N=32768 tokens.
// One CTA = 64 tokens. GEMMs via mma.sync.m16n8k8 tf32 (fp32 accum).

#define THREADS 256
#define TM 64

// smem layout in floats:
//  [0,64)    mu
//  [64,128)  rstd
//  [128,256) b_down
//  [256,384) b_up chunk
//  [384, 384+64*132)        hd tile (tf32 bits), row stride 132
//  [8832, 8832+128*132)     pool: GEMM1 {h 64x68, wd 128x68} | GEMM2 {wu 128x132}
static constexpr int SM_MU   = 0;
static constexpr int SM_RS   = 64;
static constexpr int SM_BD   = 128;
static constexpr int SM_BUP  = 256;
static constexpr int SM_HD   = 384;
static constexpr int SM_POOL = SM_HD + 64 * 132;          // 8832
static constexpr int SMEM_FLOATS = SM_POOL + 128 * 132;   // 25728
static constexpr int SMEM_BYTES = SMEM_FLOATS * 4;        // 102912

__device__ __forceinline__ uint32_t f2tf(float f) {
    uint32_t o;
    asm("cvt.rna.tf32.f32 %0, %1;" : "=r"(o) : "f"(f));
    return o;
}

__device__ __forceinline__ void mma8(float* c, const uint32_t* a, const uint32_t* b) {
    asm volatile(
        "mma.sync.aligned.m16n8k8.row.col.f32.tf32.tf32.f32 "
        "{%0,%1,%2,%3}, {%4,%5,%6,%7}, {%8,%9}, {%0,%1,%2,%3};\n"
        : "+f"(c[0]), "+f"(c[1]), "+f"(c[2]), "+f"(c[3])
        : "r"(a[0]), "r"(a[1]), "r"(a[2]), "r"(a[3]), "r"(b[0]), "r"(b[1]));
}

__global__ __launch_bounds__(THREADS, 2)
void fused_adapter_kernel(
    const float* __restrict__ x, const float* __restrict__ res,
    const float* __restrict__ gamma, const float* __restrict__ beta,
    const float* __restrict__ Wd, const float* __restrict__ bd,
    const float* __restrict__ Wu, const float* __restrict__ bup,
    float* __restrict__ out)
{
    extern __shared__ float sm[];
    const int tid  = threadIdx.x;
    const int lane = tid & 31;
    const int warp = tid >> 5;
    const int t0   = blockIdx.x * TM;

    // ---------------- Phase 0: residual add -> d_out (shortcut), LN stats ----
    #pragma unroll 1
    for (int tt = 0; tt < 8; ++tt) {
        const int tl = warp * 8 + tt;
        const int n  = t0 + tl;
        const int s  = n >> 3, b = n & 7;
        const float* xr = x   + (size_t)n * 1024;
        const float* rr = res + ((size_t)b * 4096 + (size_t)s) * 1024;
        float* orow = out + (size_t)n * 1024;
        float sum = 0.f, sq = 0.f;
        #pragma unroll 8
        for (int i = 0; i < 32; ++i) {
            const int k = i * 32 + lane;
            const float v = xr[k] + rr[k];
            orow[k] = v;
            sum += v;
            sq  += v * v;
        }
        #pragma unroll
        for (int o = 16; o > 0; o >>= 1) {
            sum += __shfl_xor_sync(0xffffffffu, sum, o);
            sq  += __shfl_xor_sync(0xffffffffu, sq, o);
        }
        if (lane == 0) {
            const float mu  = sum * (1.f / 1024.f);
            const float var = sq * (1.f / 1024.f) - mu * mu;
            sm[SM_MU + tl] = mu;
            sm[SM_RS + tl] = rsqrtf(var + 1e-5f);
        }
    }
    for (int i = tid; i < 128; i += THREADS) sm[SM_BD + i] = bd[i];
    __syncthreads();

    // warp tiling for both GEMMs: 8 warps = 2 (m) x 4 (n); warp tile 32x32
    const int mw  = warp >> 2;       // 0..1
    const int nw  = warp & 3;        // 0..3
    const int gid = lane >> 2;       // 0..7
    const int tig = lane & 3;        // 0..3

    // ---------------- GEMM1: hd[64,128] = H[64,1024] @ Wd^T ------------------
    uint32_t* sh  = (uint32_t*)(sm + SM_POOL);   // H tile [64][68]
    uint32_t* swd = sh + 64 * 68;                // Wd tile [128][68]

    float acc[2][4][4];
    #pragma unroll
    for (int i = 0; i < 2; ++i)
        #pragma unroll
        for (int j = 0; j < 4; ++j)
            #pragma unroll
            for (int q = 0; q < 4; ++q) acc[i][j][q] = 0.f;

    #pragma unroll 1
    for (int kc = 0; kc < 16; ++kc) {
        const int kg0 = kc * 64;
        // produce normalized H tile from shortcut (L2-hot)
        #pragma unroll 4
        for (int r = 0; r < 16; ++r) {
            const int idx = r * THREADS + tid;
            const int t = idx >> 6, k = idx & 63;
            const int kg = kg0 + k;
            const float v = out[(size_t)(t0 + t) * 1024 + kg];
            const float h = (v - sm[SM_MU + t]) * sm[SM_RS + t] * gamma[kg] + beta[kg];
            sh[t * 68 + k] = f2tf(h);
        }
        // produce Wd tile
        #pragma unroll 8
        for (int r = 0; r < 32; ++r) {
            const int idx = r * THREADS + tid;
            const int nn = idx >> 6, k = idx & 63;
            swd[nn * 68 + k] = f2tf(Wd[(size_t)nn * 1024 + kg0 + k]);
        }
        __syncthreads();
        #pragma unroll
        for (int ks = 0; ks < 8; ++ks) {
            const int kb = ks * 8 + tig;
            uint32_t a[2][4], bf[4][2];
            #pragma unroll
            for (int mt = 0; mt < 2; ++mt) {
                const int base = (mw * 32 + mt * 16 + gid) * 68 + kb;
                a[mt][0] = sh[base];
                a[mt][1] = sh[base + 8 * 68];
                a[mt][2] = sh[base + 4];
                a[mt][3] = sh[base + 8 * 68 + 4];
            }
            #pragma unroll
            for (int nt = 0; nt < 4; ++nt) {
                const int nb = (nw * 32 + nt * 8 + gid) * 68 + kb;
                bf[nt][0] = swd[nb];
                bf[nt][1] = swd[nb + 4];
            }
            #pragma unroll
            for (int mt = 0; mt < 2; ++mt)
                #pragma unroll
                for (int nt = 0; nt < 4; ++nt)
                    mma8(acc[mt][nt], a[mt], bf[nt]);
        }
        __syncthreads();
    }

    // epilogue GEMM1: +b_down, ReLU, store tf32 hd tile [64][132]
    uint32_t* shd = (uint32_t*)(sm + SM_HD);
    #pragma unroll
    for (int mt = 0; mt < 2; ++mt) {
        #pragma unroll
        for (int nt = 0; nt < 4; ++nt) {
            const int row = mw * 32 + mt * 16 + gid;
            const int col = nw * 32 + nt * 8 + 2 * tig;
            const float* c = acc[mt][nt];
            shd[row * 132 + col]           = f2tf(fmaxf(c[0] + sm[SM_BD + col], 0.f));
            shd[row * 132 + col + 1]       = f2tf(fmaxf(c[1] + sm[SM_BD + col + 1], 0.f));
            shd[(row + 8) * 132 + col]     = f2tf(fmaxf(c[2] + sm[SM_BD + col], 0.f));
            shd[(row + 8) * 132 + col + 1] = f2tf(fmaxf(c[3] + sm[SM_BD + col + 1], 0.f));
        }
    }
    __syncthreads();

    // ---------------- GEMM2: out[64,1024] += hd[64,128] @ Wu^T + b_up --------
    uint32_t* swu = (uint32_t*)(sm + SM_POOL);   // Wu tile [128][132]
    #pragma unroll 1
    for (int nc = 0; nc < 8; ++nc) {
        for (int i = tid; i < 128; i += THREADS) sm[SM_BUP + i] = bup[nc * 128 + i];
        // load Wu chunk [128 d][128 k] (row-major, coalesced float4)
        #pragma unroll 4
        for (int r = 0; r < 16; ++r) {
            const int idx = r * THREADS + tid;
            const int nn = idx >> 5, j = idx & 31;
            const float4 w = *(const float4*)(Wu + (size_t)(nc * 128 + nn) * 128 + j * 4);
            uint4 o;
            o.x = f2tf(w.x); o.y = f2tf(w.y); o.z = f2tf(w.z); o.w = f2tf(w.w);
            *(uint4*)(swu + nn * 132 + j * 4) = o;
        }
        __syncthreads();

        float a2[2][4][4];
        #pragma unroll
        for (int i = 0; i < 2; ++i)
            #pragma unroll
            for (int j = 0; j < 4; ++j)
                #pragma unroll
                for (int q = 0; q < 4; ++q) a2[i][j][q] = 0.f;

        #pragma unroll
        for (int ks = 0; ks < 16; ++ks) {
            const int kb = ks * 8 + tig;
            uint32_t a[2][4], bf[4][2];
            #pragma unroll
            for (int mt = 0; mt < 2; ++mt) {
                const int base = (mw * 32 + mt * 16 + gid) * 132 + kb;
                a[mt][0] = shd[base];
                a[mt][1] = shd[base + 8 * 132];
                a[mt][2] = shd[base + 4];
                a[mt][3] = shd[base + 8 * 132 + 4];
            }
            #pragma unroll
            for (int nt = 0; nt < 4; ++nt) {
                const int nb = (nw * 32 + nt * 8 + gid) * 132 + kb;
                bf[nt][0] = swu[nb];
                bf[nt][1] = swu[nb + 4];
            }
            #pragma unroll
            for (int mt = 0; mt < 2; ++mt)
                #pragma unroll
                for (int nt = 0; nt < 4; ++nt)
                    mma8(a2[mt][nt], a[mt], bf[nt]);
        }

        // epilogue: out = shortcut(d_out) + b_up + gemm2
        #pragma unroll
        for (int mt = 0; mt < 2; ++mt) {
            #pragma unroll
            for (int nt = 0; nt < 4; ++nt) {
                const int row  = mw * 32 + mt * 16 + gid;
                const int col  = nw * 32 + nt * 8 + 2 * tig;
                const int gcol = nc * 128 + col;
                const size_t off  = (size_t)(t0 + row) * 1024 + gcol;
                const size_t off2 = off + (size_t)8 * 1024;
                const float* c = a2[mt][nt];
                out[off]      = c[0] + sm[SM_BUP + col]     + out[off];
                out[off + 1]  = c[1] + sm[SM_BUP + col + 1] + out[off + 1];
                out[off2]     = c[2] + sm[SM_BUP + col]     + out[off2];
                out[off2 + 1] = c[3] + sm[SM_BUP + col + 1] + out[off2 + 1];
            }
        }
        __syncthreads();
    }
}

extern "C" void kernel_launch(void* const* d_in, const int* in_sizes, int n_in,
                              void* d_out, int out_size) {
    const float* x     = (const float*)d_in[0];
    const float* res   = (const float*)d_in[1];
    const float* gamma = (const float*)d_in[2];
    const float* beta  = (const float*)d_in[3];
    const float* Wd    = (const float*)d_in[4];
    const float* bd    = (const float*)d_in[5];
    const float* Wu    = (const float*)d_in[6];
    const float* bup   = (const float*)d_in[7];
    float* out = (float*)d_out;

    cudaFuncSetAttribute(fused_adapter_kernel,
                         cudaFuncAttributeMaxDynamicSharedMemorySize, SMEM_BYTES);
    fused_adapter_kernel<<<512, THREADS, SMEM_BYTES>>>(
        x, res, gamma, beta, Wd, bd, Wu, bup, out);
}

// round 2
// speedup vs baseline: 2.2858x; 2.2858x over previous
#include <cuda_runtime.h>
#include <cstdint>

// Fused adapter layer as a 4-kernel pipelined chain.
// S=4096, B=8, D=1024, BN=128 -> N=32768 tokens.
// 1) convert_w: Wd,Wu -> tf32 scratch
// 2) resid_ln : out = x + res^T (shortcut); H = tf32(LN(out)) -> scratch
// 3) gemm1    : hd = tf32(relu(H @ Wd^T + bd)) -> scratch   (cp.async 2-stage)
// 4) gemm2    : out += hd @ Wu^T + bup                       (one-shot K=128)

#define NTOK 32768
#define DDIM 1024
#define BN   128

__device__ __align__(16) uint32_t g_H [(size_t)NTOK * DDIM]; // normalized, tf32 bits
__device__ __align__(16) uint32_t g_hd[(size_t)NTOK * BN];   // relu'd, tf32 bits
__device__ __align__(16) uint32_t g_Wd[BN * DDIM];
__device__ __align__(16) uint32_t g_Wu[DDIM * BN];

__device__ __forceinline__ uint32_t f2tf(float f) {
    uint32_t o;
    asm("cvt.rna.tf32.f32 %0, %1;" : "=r"(o) : "f"(f));
    return o;
}

__device__ __forceinline__ void mma8(float* c, const uint32_t* a, const uint32_t* b) {
    asm volatile(
        "mma.sync.aligned.m16n8k8.row.col.f32.tf32.tf32.f32 "
        "{%0,%1,%2,%3}, {%4,%5,%6,%7}, {%8,%9}, {%0,%1,%2,%3};\n"
        : "+f"(c[0]), "+f"(c[1]), "+f"(c[2]), "+f"(c[3])
        : "r"(a[0]), "r"(a[1]), "r"(a[2]), "r"(a[3]), "r"(b[0]), "r"(b[1]));
}

__device__ __forceinline__ void cp16(void* dst_sm, const void* src) {
    uint32_t a = (uint32_t)__cvta_generic_to_shared(dst_sm);
    asm volatile("cp.async.cg.shared.global [%0], [%1], 16;\n" :: "r"(a), "l"(src));
}
__device__ __forceinline__ void cp_commit() {
    asm volatile("cp.async.commit_group;\n");
}
template <int N>
__device__ __forceinline__ void cp_wait() {
    asm volatile("cp.async.wait_group %0;\n" :: "n"(N));
}

// ------------------------------------------------------------------ kernel 1
__global__ void convert_w(const float* __restrict__ Wd, const float* __restrict__ Wu) {
    const int i = blockIdx.x * blockDim.x + threadIdx.x; // 131072 threads
    g_Wd[i] = f2tf(Wd[i]);
    g_Wu[i] = f2tf(Wu[i]);
}

// ------------------------------------------------------------------ kernel 2
// one warp per token row; row held in registers (no re-read)
__global__ __launch_bounds__(256) void resid_ln(
    const float* __restrict__ x, const float* __restrict__ res,
    const float* __restrict__ gamma, const float* __restrict__ beta,
    float* __restrict__ out)
{
    const int warp = threadIdx.x >> 5, lane = threadIdx.x & 31;
    const int n = blockIdx.x * 8 + warp;           // 4096 blocks
    const int s = n >> 3, b = n & 7;
    const float4* xr = (const float4*)(x + (size_t)n * DDIM);
    const float4* rr = (const float4*)(res + ((size_t)b * 4096 + s) * DDIM);
    float4* orow = (float4*)(out + (size_t)n * DDIM);
    uint4*  hrow = (uint4*)(g_H + (size_t)n * DDIM);
    const float4* g4 = (const float4*)gamma;
    const float4* b4 = (const float4*)beta;

    float4 v[8];
    float sum = 0.f, sq = 0.f;
    #pragma unroll
    for (int i = 0; i < 8; ++i) {
        const int k = i * 32 + lane;
        const float4 a = xr[k], r = rr[k];
        float4 t;
        t.x = a.x + r.x; t.y = a.y + r.y; t.z = a.z + r.z; t.w = a.w + r.w;
        v[i] = t;
        orow[k] = t;
        sum += t.x + t.y + t.z + t.w;
        sq  += t.x * t.x + t.y * t.y + t.z * t.z + t.w * t.w;
    }
    #pragma unroll
    for (int o = 16; o > 0; o >>= 1) {
        sum += __shfl_xor_sync(0xffffffffu, sum, o);
        sq  += __shfl_xor_sync(0xffffffffu, sq, o);
    }
    const float mu   = sum * (1.f / 1024.f);
    const float var  = sq * (1.f / 1024.f) - mu * mu;
    const float rstd = rsqrtf(var + 1e-5f);

    #pragma unroll
    for (int i = 0; i < 8; ++i) {
        const int k = i * 32 + lane;
        const float4 g = g4[k], be = b4[k];
        uint4 h;
        h.x = f2tf((v[i].x - mu) * rstd * g.x + be.x);
        h.y = f2tf((v[i].y - mu) * rstd * g.y + be.y);
        h.z = f2tf((v[i].z - mu) * rstd * g.z + be.z);
        h.w = f2tf((v[i].w - mu) * rstd * g.w + be.w);
        hrow[k] = h;
    }
}

// ------------------------------------------------------------------ kernel 3
// CTA: 64 tokens x 128(BN), K chunks of 64, 2-stage cp.async pipeline.
// smem stage: A[64][68] + B[128][68] (tf32 bits)
static constexpr int B_STG   = (64 + 128) * 68;        // 13056 u32
static constexpr int B_SMEM  = 2 * B_STG * 4;          // 104448 B

__global__ __launch_bounds__(256, 2) void gemm1(const float* __restrict__ bd)
{
    extern __shared__ uint32_t smB[];
    const int tid  = threadIdx.x;
    const int lane = tid & 31, warp = tid >> 5;
    const int t0   = blockIdx.x * 64;

    const int mw = warp >> 2, nw = warp & 3;
    const int gid = lane >> 2, tig = lane & 3;

    auto issue = [&](int s, int kc) {
        uint32_t* st = smB + s * B_STG;
        const int kg0 = kc * 64;
        #pragma unroll
        for (int p = 0; p < 4; ++p) {           // A: 64x64
            const int idx = p * 256 + tid;
            const int row = idx >> 4, j = (idx & 15) * 4;
            cp16(st + row * 68 + j, g_H + (size_t)(t0 + row) * DDIM + kg0 + j);
        }
        #pragma unroll
        for (int p = 0; p < 8; ++p) {           // B: 128x64
            const int idx = p * 256 + tid;
            const int nn = idx >> 4, j = (idx & 15) * 4;
            cp16(st + 64 * 68 + nn * 68 + j, g_Wd + (size_t)nn * DDIM + kg0 + j);
        }
        cp_commit();
    };

    float acc[2][4][4];
    #pragma unroll
    for (int i = 0; i < 2; ++i)
        #pragma unroll
        for (int j = 0; j < 4; ++j)
            #pragma unroll
            for (int q = 0; q < 4; ++q) acc[i][j][q] = 0.f;

    issue(0, 0);
    issue(1, 1);

    #pragma unroll 1
    for (int kc = 0; kc < 16; ++kc) {
        if (kc == 15) cp_wait<0>(); else cp_wait<1>();
        __syncthreads();
        const uint32_t* sa = smB + (kc & 1) * B_STG;
        const uint32_t* sb = sa + 64 * 68;
        #pragma unroll
        for (int ks = 0; ks < 8; ++ks) {
            const int kb = ks * 8 + tig;
            uint32_t a[2][4], bf[4][2];
            #pragma unroll
            for (int mt = 0; mt < 2; ++mt) {
                const int base = (mw * 32 + mt * 16 + gid) * 68 + kb;
                a[mt][0] = sa[base];
                a[mt][1] = sa[base + 8 * 68];
                a[mt][2] = sa[base + 4];
                a[mt][3] = sa[base + 8 * 68 + 4];
            }
            #pragma unroll
            for (int nt = 0; nt < 4; ++nt) {
                const int nb = (nw * 32 + nt * 8 + gid) * 68 + kb;
                bf[nt][0] = sb[nb];
                bf[nt][1] = sb[nb + 4];
            }
            #pragma unroll
            for (int mt = 0; mt < 2; ++mt)
                #pragma unroll
                for (int nt = 0; nt < 4; ++nt)
                    mma8(acc[mt][nt], a[mt], bf[nt]);
        }
        __syncthreads();
        if (kc + 2 < 16) issue((kc + 2) & 1, kc + 2);
    }

    // epilogue: +bd, relu, tf32 -> g_hd
    #pragma unroll
    for (int mt = 0; mt < 2; ++mt) {
        #pragma unroll
        for (int nt = 0; nt < 4; ++nt) {
            const int row = mw * 32 + mt * 16 + gid;
            const int col = nw * 32 + nt * 8 + 2 * tig;
            const float b0 = bd[col], b1 = bd[col + 1];
            const float* c = acc[mt][nt];
            const size_t o = (size_t)(t0 + row) * BN + col;
            g_hd[o]              = f2tf(fmaxf(c[0] + b0, 0.f));
            g_hd[o + 1]          = f2tf(fmaxf(c[1] + b1, 0.f));
            g_hd[o + 8 * BN]     = f2tf(fmaxf(c[2] + b0, 0.f));
            g_hd[o + 8 * BN + 1] = f2tf(fmaxf(c[3] + b1, 0.f));
        }
    }
}

// ------------------------------------------------------------------ kernel 4
// CTA: 64 tokens x 128 out-cols; K=128 one shot. grid (512, 8).
// smem: shd[64][132] + swu[128][132]
static constexpr int C_A     = 64 * 132;               // 8448
static constexpr int C_B     = 128 * 132;              // 16896
static constexpr int C_SMEM  = (C_A + C_B) * 4;        // 101376 B

__global__ __launch_bounds__(256, 2) void gemm2(
    const float* __restrict__ bup, float* __restrict__ out)
{
    extern __shared__ uint32_t smC[];
    uint32_t* shd = smC;
    uint32_t* swu = smC + C_A;
    const int tid  = threadIdx.x;
    const int lane = tid & 31, warp = tid >> 5;
    const int t0 = blockIdx.x * 64;
    const int nc = blockIdx.y;

    const int mw = warp >> 2, nw = warp & 3;
    const int gid = lane >> 2, tig = lane & 3;

    #pragma unroll
    for (int p = 0; p < 8; ++p) {               // hd: 64x128
        const int idx = p * 256 + tid;
        const int row = idx >> 5, j = (idx & 31) * 4;
        cp16(shd + row * 132 + j, g_hd + (size_t)(t0 + row) * BN + j);
    }
    #pragma unroll
    for (int p = 0; p < 16; ++p) {              // Wu chunk: 128x128
        const int idx = p * 256 + tid;
        const int nn = idx >> 5, j = (idx & 31) * 4;
        cp16(swu + nn * 132 + j, g_Wu + (size_t)(nc * 128 + nn) * BN + j);
    }
    cp_commit();
    cp_wait<0>();
    __syncthreads();

    float acc[2][4][4];
    #pragma unroll
    for (int i = 0; i < 2; ++i)
        #pragma unroll
        for (int j = 0; j < 4; ++j)
            #pragma unroll
            for (int q = 0; q < 4; ++q) acc[i][j][q] = 0.f;

    #pragma unroll
    for (int ks = 0; ks < 16; ++ks) {
        const int kb = ks * 8 + tig;
        uint32_t a[2][4], bf[4][2];
        #pragma unroll
        for (int mt = 0; mt < 2; ++mt) {
            const int base = (mw * 32 + mt * 16 + gid) * 132 + kb;
            a[mt][0] = shd[base];
            a[mt][1] = shd[base + 8 * 132];
            a[mt][2] = shd[base + 4];
            a[mt][3] = shd[base + 8 * 132 + 4];
        }
        #pragma unroll
        for (int nt = 0; nt < 4; ++nt) {
            const int nb = (nw * 32 + nt * 8 + gid) * 132 + kb;
            bf[nt][0] = swu[nb];
            bf[nt][1] = swu[nb + 4];
        }
        #pragma unroll
        for (int mt = 0; mt < 2; ++mt)
            #pragma unroll
            for (int nt = 0; nt < 4; ++nt)
                mma8(acc[mt][nt], a[mt], bf[nt]);
    }

    // epilogue: out = shortcut + bup + gemm2
    #pragma unroll
    for (int mt = 0; mt < 2; ++mt) {
        #pragma unroll
        for (int nt = 0; nt < 4; ++nt) {
            const int row  = mw * 32 + mt * 16 + gid;
            const int col  = nw * 32 + nt * 8 + 2 * tig;
            const int gcol = nc * 128 + col;
            const float b0 = bup[gcol], b1 = bup[gcol + 1];
            const size_t off  = (size_t)(t0 + row) * DDIM + gcol;
            const size_t off2 = off + (size_t)8 * DDIM;
            const float* c = acc[mt][nt];
            out[off]      = c[0] + b0 + out[off];
            out[off + 1]  = c[1] + b1 + out[off + 1];
            out[off2]     = c[2] + b0 + out[off2];
            out[off2 + 1] = c[3] + b1 + out[off2 + 1];
        }
    }
}

// ------------------------------------------------------------------ launch
extern "C" void kernel_launch(void* const* d_in, const int* in_sizes, int n_in,
                              void* d_out, int out_size) {
    const float* x     = (const float*)d_in[0];
    const float* res   = (const float*)d_in[1];
    const float* gamma = (const float*)d_in[2];
    const float* beta  = (const float*)d_in[3];
    const float* Wd    = (const float*)d_in[4];
    const float* bd    = (const float*)d_in[5];
    const float* Wu    = (const float*)d_in[6];
    const float* bup   = (const float*)d_in[7];
    float* out = (float*)d_out;

    static bool attr_done = false;
    if (!attr_done) {
        cudaFuncSetAttribute(gemm1, cudaFuncAttributeMaxDynamicSharedMemorySize, B_SMEM);
        cudaFuncSetAttribute(gemm2, cudaFuncAttributeMaxDynamicSharedMemorySize, C_SMEM);
        attr_done = true;
    }

    convert_w<<<512, 256>>>(Wd, Wu);
    resid_ln<<<4096, 256>>>(x, res, gamma, beta, out);
    gemm1<<<512, 256, B_SMEM>>>(bd);
    gemm2<<<dim3(512, 8), 256, C_SMEM>>>(bup, out);
}

// round 3
// speedup vs baseline: 3.2263x; 1.4114x over previous
#include <cuda_runtime.h>
#include <cuda_fp16.h>
#include <cstdint>

// Fused adapter layer, 4-kernel chain, fp16 tensor-core datapath (m16n8k16).
// S=4096, B=8, D=1024, BN=128 -> N=32768 tokens.
// 1) convert_w: Wd,Wu -> half scratch
// 2) resid_ln : out = x + res^T (shortcut, fp32); H = half(LN(out)) -> scratch
// 3) gemm1    : hd = half(relu(H @ Wd^T + bd)) -> scratch   (cp.async 2-stage)
// 4) gemm2    : out += hd @ Wu^T + bup                       (K split, 2 groups)

#define NTOK 32768
#define DDIM 1024
#define BN   128

__device__ __align__(16) __half g_H [(size_t)NTOK * DDIM];
__device__ __align__(16) __half g_hd[(size_t)NTOK * BN];
__device__ __align__(16) __half g_Wd[BN * DDIM];
__device__ __align__(16) __half g_Wu[DDIM * BN];

__device__ __forceinline__ void mma16(float* c, const uint32_t* a, const uint32_t* b) {
    asm volatile(
        "mma.sync.aligned.m16n8k16.row.col.f32.f16.f16.f32 "
        "{%0,%1,%2,%3}, {%4,%5,%6,%7}, {%8,%9}, {%0,%1,%2,%3};\n"
        : "+f"(c[0]), "+f"(c[1]), "+f"(c[2]), "+f"(c[3])
        : "r"(a[0]), "r"(a[1]), "r"(a[2]), "r"(a[3]), "r"(b[0]), "r"(b[1]));
}

__device__ __forceinline__ uint32_t ldsm_u32(const __half* p) {
    return *(const uint32_t*)p;
}

__device__ __forceinline__ void cp16(void* dst_sm, const void* src) {
    uint32_t a = (uint32_t)__cvta_generic_to_shared(dst_sm);
    asm volatile("cp.async.cg.shared.global [%0], [%1], 16;\n" :: "r"(a), "l"(src));
}
__device__ __forceinline__ void cp_commit() {
    asm volatile("cp.async.commit_group;\n");
}
template <int N>
__device__ __forceinline__ void cp_wait() {
    asm volatile("cp.async.wait_group %0;\n" :: "n"(N));
}

// ------------------------------------------------------------------ kernel 1
__global__ void convert_w(const float* __restrict__ Wd, const float* __restrict__ Wu) {
    const int i = blockIdx.x * blockDim.x + threadIdx.x; // 131072 threads
    g_Wd[i] = __float2half_rn(Wd[i]);
    g_Wu[i] = __float2half_rn(Wu[i]);
}

// ------------------------------------------------------------------ kernel 2
// one warp per token row; row held in registers (no re-read)
__global__ __launch_bounds__(256) void resid_ln(
    const float* __restrict__ x, const float* __restrict__ res,
    const float* __restrict__ gamma, const float* __restrict__ beta,
    float* __restrict__ out)
{
    const int warp = threadIdx.x >> 5, lane = threadIdx.x & 31;
    const int n = blockIdx.x * 8 + warp;           // 4096 blocks
    const int s = n >> 3, b = n & 7;
    const float4* xr = (const float4*)(x + (size_t)n * DDIM);
    const float4* rr = (const float4*)(res + ((size_t)b * 4096 + s) * DDIM);
    float4* orow = (float4*)(out + (size_t)n * DDIM);
    uint2*  hrow = (uint2*)(g_H + (size_t)n * DDIM);
    const float4* g4 = (const float4*)gamma;
    const float4* b4 = (const float4*)beta;

    float4 v[8];
    float sum = 0.f, sq = 0.f;
    #pragma unroll
    for (int i = 0; i < 8; ++i) {
        const int k = i * 32 + lane;
        const float4 a = xr[k], r = rr[k];
        float4 t;
        t.x = a.x + r.x; t.y = a.y + r.y; t.z = a.z + r.z; t.w = a.w + r.w;
        v[i] = t;
        orow[k] = t;
        sum += t.x + t.y + t.z + t.w;
        sq  += t.x * t.x + t.y * t.y + t.z * t.z + t.w * t.w;
    }
    #pragma unroll
    for (int o = 16; o > 0; o >>= 1) {
        sum += __shfl_xor_sync(0xffffffffu, sum, o);
        sq  += __shfl_xor_sync(0xffffffffu, sq, o);
    }
    const float mu   = sum * (1.f / 1024.f);
    const float var  = sq * (1.f / 1024.f) - mu * mu;
    const float rstd = rsqrtf(var + 1e-5f);

    #pragma unroll
    for (int i = 0; i < 8; ++i) {
        const int k = i * 32 + lane;
        const float4 g = g4[k], be = b4[k];
        __half2 h0 = __floats2half2_rn((v[i].x - mu) * rstd * g.x + be.x,
                                       (v[i].y - mu) * rstd * g.y + be.y);
        __half2 h1 = __floats2half2_rn((v[i].z - mu) * rstd * g.z + be.z,
                                       (v[i].w - mu) * rstd * g.w + be.w);
        uint2 u;
        u.x = *(uint32_t*)&h0;
        u.y = *(uint32_t*)&h1;
        hrow[k] = u;
    }
}

// ------------------------------------------------------------------ kernel 3
// CTA: 64 tokens x 128(BN). K chunks of 64 halves, 2-stage cp.async pipeline.
// smem stage: A[64][72] + B[128][72] (half), pad 8 -> conflict-free frag loads.
static constexpr int G1_AST  = 72;                     // A row stride (halves)
static constexpr int G1_STG  = (64 + 128) * G1_AST;    // halves per stage
static constexpr int G1_SMEM = 2 * G1_STG * 2;         // 55296 B

__global__ __launch_bounds__(256, 3) void gemm1(const float* __restrict__ bd)
{
    extern __shared__ __half smB[];
    const int tid  = threadIdx.x;
    const int lane = tid & 31, warp = tid >> 5;
    const int t0   = blockIdx.x * 64;

    const int mw = warp >> 2, nw = warp & 3;
    const int gid = lane >> 2, tig = lane & 3;

    auto issue = [&](int st, int kc) {
        __half* s = smB + st * G1_STG;
        const int kg0 = kc * 64;
        #pragma unroll
        for (int p = 0; p < 2; ++p) {           // A: 64 x 64 halves
            const int idx = p * 256 + tid;
            const int row = idx >> 3, j = (idx & 7) * 8;
            cp16(s + row * G1_AST + j, g_H + (size_t)(t0 + row) * DDIM + kg0 + j);
        }
        #pragma unroll
        for (int p = 0; p < 4; ++p) {           // B: 128 x 64 halves
            const int idx = p * 256 + tid;
            const int nn = idx >> 3, j = (idx & 7) * 8;
            cp16(s + 64 * G1_AST + nn * G1_AST + j, g_Wd + (size_t)nn * DDIM + kg0 + j);
        }
        cp_commit();
    };

    float acc[2][4][4];
    #pragma unroll
    for (int i = 0; i < 2; ++i)
        #pragma unroll
        for (int j = 0; j < 4; ++j)
            #pragma unroll
            for (int q = 0; q < 4; ++q) acc[i][j][q] = 0.f;

    issue(0, 0);
    issue(1, 1);

    #pragma unroll 1
    for (int kc = 0; kc < 16; ++kc) {
        if (kc == 15) cp_wait<0>(); else cp_wait<1>();
        __syncthreads();
        const __half* sa = smB + (kc & 1) * G1_STG;
        const __half* sb = sa + 64 * G1_AST;
        #pragma unroll
        for (int ks = 0; ks < 4; ++ks) {        // 4 x k16 = 64
            const int kb = ks * 16 + 2 * tig;
            uint32_t a[2][4], bf[4][2];
            #pragma unroll
            for (int mt = 0; mt < 2; ++mt) {
                const int base = (mw * 32 + mt * 16 + gid) * G1_AST + kb;
                a[mt][0] = ldsm_u32(sa + base);
                a[mt][1] = ldsm_u32(sa + base + 8 * G1_AST);
                a[mt][2] = ldsm_u32(sa + base + 8);
                a[mt][3] = ldsm_u32(sa + base + 8 * G1_AST + 8);
            }
            #pragma unroll
            for (int nt = 0; nt < 4; ++nt) {
                const int nb = (nw * 32 + nt * 8 + gid) * G1_AST + kb;
                bf[nt][0] = ldsm_u32(sb + nb);
                bf[nt][1] = ldsm_u32(sb + nb + 8);
            }
            #pragma unroll
            for (int mt = 0; mt < 2; ++mt)
                #pragma unroll
                for (int nt = 0; nt < 4; ++nt)
                    mma16(acc[mt][nt], a[mt], bf[nt]);
        }
        __syncthreads();
        if (kc + 2 < 16) issue((kc + 2) & 1, kc + 2);
    }

    // epilogue: +bd, relu, half -> g_hd
    #pragma unroll
    for (int mt = 0; mt < 2; ++mt) {
        #pragma unroll
        for (int nt = 0; nt < 4; ++nt) {
            const int row = mw * 32 + mt * 16 + gid;
            const int col = nw * 32 + nt * 8 + 2 * tig;
            const float b0 = bd[col], b1 = bd[col + 1];
            const float* c = acc[mt][nt];
            const size_t o = (size_t)(t0 + row) * BN + col;
            __half2 h0 = __floats2half2_rn(fmaxf(c[0] + b0, 0.f), fmaxf(c[1] + b1, 0.f));
            __half2 h1 = __floats2half2_rn(fmaxf(c[2] + b0, 0.f), fmaxf(c[3] + b1, 0.f));
            *(uint32_t*)(g_hd + o)          = *(uint32_t*)&h0;
            *(uint32_t*)(g_hd + o + 8 * BN) = *(uint32_t*)&h1;
        }
    }
}

// ------------------------------------------------------------------ kernel 4
// CTA: 64 tokens x 128 out-cols; K=128 split into 2 cp.async groups. grid (512,8).
// smem: shd[64][136] + swu[128][136] halves
static constexpr int G2_ST   = 136;
static constexpr int G2_A    = 64 * G2_ST;
static constexpr int G2_SMEM = (64 + 128) * G2_ST * 2; // 52224 B

__global__ __launch_bounds__(256, 3) void gemm2(
    const float* __restrict__ bup, float* __restrict__ out)
{
    extern __shared__ __half smC[];
    __half* shd = smC;
    __half* swu = smC + G2_A;
    const int tid  = threadIdx.x;
    const int lane = tid & 31, warp = tid >> 5;
    const int t0 = blockIdx.x * 64;
    const int nc = blockIdx.y;

    const int mw = warp >> 2, nw = warp & 3;
    const int gid = lane >> 2, tig = lane & 3;

    // group 0: K cols [0,64) of both tiles; group 1: [64,128)
    #pragma unroll
    for (int half_k = 0; half_k < 2; ++half_k) {
        const int k0 = half_k * 64;
        #pragma unroll
        for (int p = 0; p < 2; ++p) {           // hd: 64 rows x 64 halves
            const int idx = p * 256 + tid;
            const int row = idx >> 3, j = (idx & 7) * 8;
            cp16(shd + row * G2_ST + k0 + j, g_hd + (size_t)(t0 + row) * BN + k0 + j);
        }
        #pragma unroll
        for (int p = 0; p < 4; ++p) {           // Wu: 128 rows x 64 halves
            const int idx = p * 256 + tid;
            const int nn = idx >> 3, j = (idx & 7) * 8;
            cp16(swu + nn * G2_ST + k0 + j,
                 g_Wu + (size_t)(nc * 128 + nn) * BN + k0 + j);
        }
        cp_commit();
    }

    float acc[2][4][4];
    #pragma unroll
    for (int i = 0; i < 2; ++i)
        #pragma unroll
        for (int j = 0; j < 4; ++j)
            #pragma unroll
            for (int q = 0; q < 4; ++q) acc[i][j][q] = 0.f;

    #pragma unroll
    for (int hk = 0; hk < 2; ++hk) {
        if (hk == 0) cp_wait<1>(); else cp_wait<0>();
        __syncthreads();
        #pragma unroll
        for (int ks = 0; ks < 4; ++ks) {
            const int kb = hk * 64 + ks * 16 + 2 * tig;
            uint32_t a[2][4], bf[4][2];
            #pragma unroll
            for (int mt = 0; mt < 2; ++mt) {
                const int base = (mw * 32 + mt * 16 + gid) * G2_ST + kb;
                a[mt][0] = ldsm_u32(shd + base);
                a[mt][1] = ldsm_u32(shd + base + 8 * G2_ST);
                a[mt][2] = ldsm_u32(shd + base + 8);
                a[mt][3] = ldsm_u32(shd + base + 8 * G2_ST + 8);
            }
            #pragma unroll
            for (int nt = 0; nt < 4; ++nt) {
                const int nb = (nw * 32 + nt * 8 + gid) * G2_ST + kb;
                bf[nt][0] = ldsm_u32(swu + nb);
                bf[nt][1] = ldsm_u32(swu + nb + 8);
            }
            #pragma unroll
            for (int mt = 0; mt < 2; ++mt)
                #pragma unroll
                for (int nt = 0; nt < 4; ++nt)
                    mma16(acc[mt][nt], a[mt], bf[nt]);
        }
    }

    // epilogue: out = shortcut + bup + gemm2
    #pragma unroll
    for (int mt = 0; mt < 2; ++mt) {
        #pragma unroll
        for (int nt = 0; nt < 4; ++nt) {
            const int row  = mw * 32 + mt * 16 + gid;
            const int col  = nw * 32 + nt * 8 + 2 * tig;
            const int gcol = nc * 128 + col;
            const float b0 = bup[gcol], b1 = bup[gcol + 1];
            const size_t off  = (size_t)(t0 + row) * DDIM + gcol;
            const size_t off2 = off + (size_t)8 * DDIM;
            const float* c = acc[mt][nt];
            out[off]      = c[0] + b0 + out[off];
            out[off + 1]  = c[1] + b1 + out[off + 1];
            out[off2]     = c[2] + b0 + out[off2];
            out[off2 + 1] = c[3] + b1 + out[off2 + 1];
        }
    }
}

// ------------------------------------------------------------------ launch
extern "C" void kernel_launch(void* const* d_in, const int* in_sizes, int n_in,
                              void* d_out, int out_size) {
    const float* x     = (const float*)d_in[0];
    const float* res   = (const float*)d_in[1];
    const float* gamma = (const float*)d_in[2];
    const float* beta  = (const float*)d_in[3];
    const float* Wd    = (const float*)d_in[4];
    const float* bd    = (const float*)d_in[5];
    const float* Wu    = (const float*)d_in[6];
    const float* bup   = (const float*)d_in[7];
    float* out = (float*)d_out;

    static bool attr_done = false;
    if (!attr_done) {
        cudaFuncSetAttribute(gemm1, cudaFuncAttributeMaxDynamicSharedMemorySize, G1_SMEM);
        cudaFuncSetAttribute(gemm2, cudaFuncAttributeMaxDynamicSharedMemorySize, G2_SMEM);
        attr_done = true;
    }

    convert_w<<<512, 256>>>(Wd, Wu);
    resid_ln<<<4096, 256>>>(x, res, gamma, beta, out);
    gemm1<<<512, 256, G1_SMEM>>>(bd);
    gemm2<<<dim3(512, 8), 256, G2_SMEM>>>(bup, out);
}

// round 4
// speedup vs baseline: 3.9425x; 1.2220x over previous
#include <cuda_runtime.h>
#include <cuda_fp16.h>
#include <cstdint>

// Fused adapter layer, 4-kernel chain, fp16 tensor cores + ldmatrix.
// 1) convert_w: Wd,Wu -> half scratch
// 2) resid_ln : out = x + res^T (shortcut, fp32); H = half(LN(out)) -> scratch
// 3) gemm1    : hd = half(relu(H @ Wd^T + bd))  (cp.async 2-stage, LDSM)
// 4) gemm2    : out += hd @ Wu^T + bup          (LDSM, shortcut prefetched)

#define NTOK 32768
#define DDIM 1024
#define BN   128

__device__ __align__(16) __half g_H [(size_t)NTOK * DDIM];
__device__ __align__(16) __half g_hd[(size_t)NTOK * BN];
__device__ __align__(16) __half g_Wd[BN * DDIM];
__device__ __align__(16) __half g_Wu[DDIM * BN];

__device__ __forceinline__ void mma16(float* c, const uint32_t* a, const uint32_t* b) {
    asm volatile(
        "mma.sync.aligned.m16n8k16.row.col.f32.f16.f16.f32 "
        "{%0,%1,%2,%3}, {%4,%5,%6,%7}, {%8,%9}, {%0,%1,%2,%3};\n"
        : "+f"(c[0]), "+f"(c[1]), "+f"(c[2]), "+f"(c[3])
        : "r"(a[0]), "r"(a[1]), "r"(a[2]), "r"(a[3]), "r"(b[0]), "r"(b[1]));
}

__device__ __forceinline__ void ldsm4(uint32_t* r, const __half* p) {
    uint32_t a = (uint32_t)__cvta_generic_to_shared(p);
    asm volatile("ldmatrix.sync.aligned.m8n8.x4.shared.b16 {%0,%1,%2,%3}, [%4];\n"
                 : "=r"(r[0]), "=r"(r[1]), "=r"(r[2]), "=r"(r[3]) : "r"(a));
}

__device__ __forceinline__ void cp16(void* dst_sm, const void* src) {
    uint32_t a = (uint32_t)__cvta_generic_to_shared(dst_sm);
    asm volatile("cp.async.cg.shared.global [%0], [%1], 16;\n" :: "r"(a), "l"(src));
}
__device__ __forceinline__ void cp_commit() {
    asm volatile("cp.async.commit_group;\n");
}
template <int N>
__device__ __forceinline__ void cp_wait() {
    asm volatile("cp.async.wait_group %0;\n" :: "n"(N));
}

// ------------------------------------------------------------------ kernel 1
__global__ void convert_w(const float* __restrict__ Wd, const float* __restrict__ Wu) {
    const int i = blockIdx.x * blockDim.x + threadIdx.x; // 131072 threads
    g_Wd[i] = __float2half_rn(Wd[i]);
    g_Wu[i] = __float2half_rn(Wu[i]);
}

// ------------------------------------------------------------------ kernel 2
__global__ __launch_bounds__(256) void resid_ln(
    const float* __restrict__ x, const float* __restrict__ res,
    const float* __restrict__ gamma, const float* __restrict__ beta,
    float* __restrict__ out)
{
    const int warp = threadIdx.x >> 5, lane = threadIdx.x & 31;
    const int n = blockIdx.x * 8 + warp;           // 4096 blocks
    const int s = n >> 3, b = n & 7;
    const float4* xr = (const float4*)(x + (size_t)n * DDIM);
    const float4* rr = (const float4*)(res + ((size_t)b * 4096 + s) * DDIM);
    float4* orow = (float4*)(out + (size_t)n * DDIM);
    uint2*  hrow = (uint2*)(g_H + (size_t)n * DDIM);
    const float4* g4 = (const float4*)gamma;
    const float4* b4 = (const float4*)beta;

    float4 v[8];
    float sum = 0.f, sq = 0.f;
    #pragma unroll
    for (int i = 0; i < 8; ++i) {
        const int k = i * 32 + lane;
        const float4 a = xr[k], r = rr[k];
        float4 t;
        t.x = a.x + r.x; t.y = a.y + r.y; t.z = a.z + r.z; t.w = a.w + r.w;
        v[i] = t;
        orow[k] = t;
        sum += t.x + t.y + t.z + t.w;
        sq  += t.x * t.x + t.y * t.y + t.z * t.z + t.w * t.w;
    }
    #pragma unroll
    for (int o = 16; o > 0; o >>= 1) {
        sum += __shfl_xor_sync(0xffffffffu, sum, o);
        sq  += __shfl_xor_sync(0xffffffffu, sq, o);
    }
    const float mu   = sum * (1.f / 1024.f);
    const float var  = sq * (1.f / 1024.f) - mu * mu;
    const float rstd = rsqrtf(var + 1e-5f);

    #pragma unroll
    for (int i = 0; i < 8; ++i) {
        const int k = i * 32 + lane;
        const float4 g = g4[k], be = b4[k];
        __half2 h0 = __floats2half2_rn((v[i].x - mu) * rstd * g.x + be.x,
                                       (v[i].y - mu) * rstd * g.y + be.y);
        __half2 h1 = __floats2half2_rn((v[i].z - mu) * rstd * g.z + be.z,
                                       (v[i].w - mu) * rstd * g.w + be.w);
        uint2 u;
        u.x = *(uint32_t*)&h0;
        u.y = *(uint32_t*)&h1;
        hrow[k] = u;
    }
}

// ------------------------------------------------------------------ kernel 3
// CTA: 64 tokens x 128(BN). K chunks of 64 halves, 2-stage cp.async pipeline.
static constexpr int G1_AST  = 72;                     // row stride (halves)
static constexpr int G1_STG  = (64 + 128) * G1_AST;    // halves per stage
static constexpr int G1_SMEM = 2 * G1_STG * 2;         // 55296 B

__global__ __launch_bounds__(256, 3) void gemm1(const float* __restrict__ bd)
{
    extern __shared__ __half smB[];
    const int tid  = threadIdx.x;
    const int lane = tid & 31, warp = tid >> 5;
    const int t0   = blockIdx.x * 64;

    const int mw = warp >> 2, nw = warp & 3;
    const int gid = lane >> 2, tig = lane & 3;

    // ldmatrix lane addressing offsets
    const int a_row = (lane & 7) + ((lane >> 3) & 1) * 8;   // within 16-row tile
    const int a_kof = (lane >> 4) * 8;
    const int b_row = (lane & 7) + (lane >> 4) * 8;         // within 16-row n pair
    const int b_kof = ((lane >> 3) & 1) * 8;

    auto issue = [&](int st, int kc) {
        __half* s = smB + st * G1_STG;
        const int kg0 = kc * 64;
        #pragma unroll
        for (int p = 0; p < 2; ++p) {           // A: 64 x 64 halves
            const int idx = p * 256 + tid;
            const int row = idx >> 3, j = (idx & 7) * 8;
            cp16(s + row * G1_AST + j, g_H + (size_t)(t0 + row) * DDIM + kg0 + j);
        }
        #pragma unroll
        for (int p = 0; p < 4; ++p) {           // B: 128 x 64 halves
            const int idx = p * 256 + tid;
            const int nn = idx >> 3, j = (idx & 7) * 8;
            cp16(s + 64 * G1_AST + nn * G1_AST + j, g_Wd + (size_t)nn * DDIM + kg0 + j);
        }
        cp_commit();
    };

    float acc[2][4][4];
    #pragma unroll
    for (int i = 0; i < 2; ++i)
        #pragma unroll
        for (int j = 0; j < 4; ++j)
            #pragma unroll
            for (int q = 0; q < 4; ++q) acc[i][j][q] = 0.f;

    issue(0, 0);
    issue(1, 1);

    #pragma unroll 1
    for (int kc = 0; kc < 16; ++kc) {
        if (kc == 15) cp_wait<0>(); else cp_wait<1>();
        __syncthreads();
        const __half* sa = smB + (kc & 1) * G1_STG;
        const __half* sb = sa + 64 * G1_AST;
        #pragma unroll
        for (int ks = 0; ks < 4; ++ks) {        // 4 x k16 = 64
            const int kb0 = ks * 16;
            uint32_t a[2][4], bf[2][4];
            #pragma unroll
            for (int mt = 0; mt < 2; ++mt)
                ldsm4(a[mt], sa + (mw * 32 + mt * 16 + a_row) * G1_AST + kb0 + a_kof);
            #pragma unroll
            for (int nt2 = 0; nt2 < 2; ++nt2)
                ldsm4(bf[nt2], sb + (nw * 32 + nt2 * 16 + b_row) * G1_AST + kb0 + b_kof);
            #pragma unroll
            for (int mt = 0; mt < 2; ++mt)
                #pragma unroll
                for (int nt = 0; nt < 4; ++nt)
                    mma16(acc[mt][nt], a[mt], bf[nt >> 1] + (nt & 1) * 2);
        }
        __syncthreads();
        if (kc + 2 < 16) issue((kc + 2) & 1, kc + 2);
    }

    // epilogue: +bd, relu, half -> g_hd
    #pragma unroll
    for (int mt = 0; mt < 2; ++mt) {
        #pragma unroll
        for (int nt = 0; nt < 4; ++nt) {
            const int row = mw * 32 + mt * 16 + gid;
            const int col = nw * 32 + nt * 8 + 2 * tig;
            const float b0 = bd[col], b1 = bd[col + 1];
            const float* c = acc[mt][nt];
            const size_t o = (size_t)(t0 + row) * BN + col;
            __half2 h0 = __floats2half2_rn(fmaxf(c[0] + b0, 0.f), fmaxf(c[1] + b1, 0.f));
            __half2 h1 = __floats2half2_rn(fmaxf(c[2] + b0, 0.f), fmaxf(c[3] + b1, 0.f));
            *(uint32_t*)(g_hd + o)          = *(uint32_t*)&h0;
            *(uint32_t*)(g_hd + o + 8 * BN) = *(uint32_t*)&h1;
        }
    }
}

// ------------------------------------------------------------------ kernel 4
// CTA: 64 tokens x 128 out-cols; K=128; shortcut prefetched via cp.async.
// smem: shd[64][136]h + swu[128][136]h + sout[64][132]f + sbup[128]f
static constexpr int G2_ST    = 136;
static constexpr int G2_A     = 64 * G2_ST;
static constexpr int G2_HB    = (64 + 128) * G2_ST;    // halves
static constexpr int G2_OUT   = 64 * 132;              // floats
static constexpr int G2_SMEM  = G2_HB * 2 + (G2_OUT + 128) * 4; // 86528 B

__global__ __launch_bounds__(256, 2) void gemm2(
    const float* __restrict__ bup, float* __restrict__ out)
{
    extern __shared__ __half smC[];
    __half* shd = smC;
    __half* swu = smC + G2_A;
    float*  sout = (float*)(smC + G2_HB);
    float*  sbup = sout + G2_OUT;
    const int tid  = threadIdx.x;
    const int lane = tid & 31, warp = tid >> 5;
    const int t0 = blockIdx.x * 64;
    const int nc = blockIdx.y;

    const int mw = warp >> 2, nw = warp & 3;
    const int gid = lane >> 2, tig = lane & 3;

    const int a_row = (lane & 7) + ((lane >> 3) & 1) * 8;
    const int a_kof = (lane >> 4) * 8;
    const int b_row = (lane & 7) + (lane >> 4) * 8;
    const int b_kof = ((lane >> 3) & 1) * 8;

    // groups 0,1: tiles (K halves); group 2: shortcut + bup
    #pragma unroll
    for (int hk = 0; hk < 2; ++hk) {
        const int k0 = hk * 64;
        #pragma unroll
        for (int p = 0; p < 2; ++p) {           // hd: 64 x 64 halves
            const int idx = p * 256 + tid;
            const int row = idx >> 3, j = (idx & 7) * 8;
            cp16(shd + row * G2_ST + k0 + j, g_hd + (size_t)(t0 + row) * BN + k0 + j);
        }
        #pragma unroll
        for (int p = 0; p < 4; ++p) {           // Wu: 128 x 64 halves
            const int idx = p * 256 + tid;
            const int nn = idx >> 3, j = (idx & 7) * 8;
            cp16(swu + nn * G2_ST + k0 + j,
                 g_Wu + (size_t)(nc * 128 + nn) * BN + k0 + j);
        }
        cp_commit();
    }
    #pragma unroll
    for (int p = 0; p < 8; ++p) {               // shortcut: 64 x 128 floats
        const int idx = p * 256 + tid;
        const int row = idx >> 5, j = (idx & 31) * 4;
        cp16(sout + row * 132 + j, out + (size_t)(t0 + row) * DDIM + nc * 128 + j);
    }
    if (tid < 32) cp16(sbup + tid * 4, bup + nc * 128 + tid * 4);
    cp_commit();

    float acc[2][4][4];
    #pragma unroll
    for (int i = 0; i < 2; ++i)
        #pragma unroll
        for (int j = 0; j < 4; ++j)
            #pragma unroll
            for (int q = 0; q < 4; ++q) acc[i][j][q] = 0.f;

    #pragma unroll
    for (int hk = 0; hk < 2; ++hk) {
        if (hk == 0) cp_wait<2>(); else cp_wait<1>();
        __syncthreads();
        #pragma unroll
        for (int ks = 0; ks < 4; ++ks) {
            const int kb0 = hk * 64 + ks * 16;
            uint32_t a[2][4], bf[2][4];
            #pragma unroll
            for (int mt = 0; mt < 2; ++mt)
                ldsm4(a[mt], shd + (mw * 32 + mt * 16 + a_row) * G2_ST + kb0 + a_kof);
            #pragma unroll
            for (int nt2 = 0; nt2 < 2; ++nt2)
                ldsm4(bf[nt2], swu + (nw * 32 + nt2 * 16 + b_row) * G2_ST + kb0 + b_kof);
            #pragma unroll
            for (int mt = 0; mt < 2; ++mt)
                #pragma unroll
                for (int nt = 0; nt < 4; ++nt)
                    mma16(acc[mt][nt], a[mt], bf[nt >> 1] + (nt & 1) * 2);
        }
    }

    cp_wait<0>();
    __syncthreads();

    // epilogue: out = shortcut(smem) + bup + gemm2, float2 stores
    #pragma unroll
    for (int mt = 0; mt < 2; ++mt) {
        #pragma unroll
        for (int nt = 0; nt < 4; ++nt) {
            const int row  = mw * 32 + mt * 16 + gid;
            const int col  = nw * 32 + nt * 8 + 2 * tig;
            const int gcol = nc * 128 + col;
            const float b0 = sbup[col], b1 = sbup[col + 1];
            const size_t off  = (size_t)(t0 + row) * DDIM + gcol;
            const size_t off2 = off + (size_t)8 * DDIM;
            const float* c = acc[mt][nt];
            const float2 s0 = *(const float2*)(sout + row * 132 + col);
            const float2 s1 = *(const float2*)(sout + (row + 8) * 132 + col);
            float2 o0, o1;
            o0.x = c[0] + b0 + s0.x; o0.y = c[1] + b1 + s0.y;
            o1.x = c[2] + b0 + s1.x; o1.y = c[3] + b1 + s1.y;
            *(float2*)(out + off)  = o0;
            *(float2*)(out + off2) = o1;
        }
    }
}

// ------------------------------------------------------------------ launch
extern "C" void kernel_launch(void* const* d_in, const int* in_sizes, int n_in,
                              void* d_out, int out_size) {
    const float* x     = (const float*)d_in[0];
    const float* res   = (const float*)d_in[1];
    const float* gamma = (const float*)d_in[2];
    const float* beta  = (const float*)d_in[3];
    const float* Wd    = (const float*)d_in[4];
    const float* bd    = (const float*)d_in[5];
    const float* Wu    = (const float*)d_in[6];
    const float* bup   = (const float*)d_in[7];
    float* out = (float*)d_out;

    static bool attr_done = false;
    if (!attr_done) {
        cudaFuncSetAttribute(gemm1, cudaFuncAttributeMaxDynamicSharedMemorySize, G1_SMEM);
        cudaFuncSetAttribute(gemm2, cudaFuncAttributeMaxDynamicSharedMemorySize, G2_SMEM);
        attr_done = true;
    }

    convert_w<<<512, 256>>>(Wd, Wu);
    resid_ln<<<4096, 256>>>(x, res, gamma, beta, out);
    gemm1<<<512, 256, G1_SMEM>>>(bd);
    gemm2<<<dim3(512, 8), 256, G2_SMEM>>>(bup, out);
}